// round 7
// baseline (speedup 1.0000x reference)
#include <cuda_runtime.h>
#include <cuda_bf16.h>
#include <cstdint>
#include <math.h>

#define B_   8192
#define T_   10
#define F_   561
#define H_   256
#define O_   12
#define G4H  1024
#define NBT  (B_ * T_)          // 81920
#define KX   1728               // 3*561=1683 padded to mult of 64
#define K3H  768                // 3*256
#define K6H  1536               // 6*256

#define SWZ128(off) ((off) ^ (((off) >> 3) & 0x70))

__device__ __forceinline__ uint32_t smem_u32(const void* p) {
    uint32_t a;
    asm("{ .reg .u64 t; cvta.to.shared.u64 t, %1; cvt.u32.u64 %0, t; }" : "=r"(a) : "l"(p));
    return a;
}
__device__ __forceinline__ void ldsm_x4(uint32_t* r, uint32_t addr) {
    asm volatile("ldmatrix.sync.aligned.m8n8.x4.shared.b16 {%0,%1,%2,%3}, [%4];"
                 : "=r"(r[0]), "=r"(r[1]), "=r"(r[2]), "=r"(r[3]) : "r"(addr));
}
__device__ __forceinline__ void mma_bf16(float* d, const uint32_t* a, uint32_t b0, uint32_t b1) {
    asm volatile("mma.sync.aligned.m16n8k16.row.col.f32.bf16.bf16.f32 "
                 "{%0,%1,%2,%3}, {%4,%5,%6,%7}, {%8,%9}, {%0,%1,%2,%3};"
                 : "+f"(d[0]), "+f"(d[1]), "+f"(d[2]), "+f"(d[3])
                 : "r"(a[0]), "r"(a[1]), "r"(a[2]), "r"(a[3]), "r"(b0), "r"(b1));
}

// ======================= scratch =======================
__device__ __nv_bfloat16 g_Xsplit[(size_t)NBT * KX];
__device__ __nv_bfloat16 g_Axp[(size_t)NBT * K3H];        // [NBT,768] = [xp_hi|xp_hi|xp_lo]
__device__ float         g_xp[(size_t)NBT * H_];
__device__ __nv_bfloat16 g_ActA[(size_t)B_ * K6H];        // [B,1536]: [h0 hhl | h1 hhl]
__device__ __nv_bfloat16 g_ActB[(size_t)B_ * K6H];
__device__ float         g_c0[B_ * H_];
__device__ float         g_c1[B_ * H_];
__device__ float         g_hs[(size_t)NBT * H_];
__device__ __nv_bfloat16 g_WbInp[(size_t)H_ * KX];        // [256,1728] = [Whi|Wlo|Whi|pad]
__device__ __nv_bfloat16 g_Wc0[(size_t)G4H * K6H];        // gate-interleaved [Wih0 hlh | Whh0 hlh]
__device__ __nv_bfloat16 g_Wc1[(size_t)G4H * K6H];        // gate-interleaved [Wih1 hlh | Whh1 hlh]
__device__ float         g_bias0[G4H];                    // interleaved bih0+bhh0
__device__ float         g_bias1[G4H];

// ======================= tile config =======================
#define TM_ 128
#define TN_ 128
#define KC  64
#define SM_A0  0
#define SM_A1  16384
#define SM_B0  32768
#define SM_B1  49152
#define SM_TOTAL 65536
#define STAGE_LD 72   // floats per stage row (16B-aligned stride, conflict-friendly)

__device__ __forceinline__ float sigmoidf_(float x) { return 1.0f / (1.0f + expf(-x)); }
__device__ __forceinline__ void split_bf16(float x, __nv_bfloat16& hi, __nv_bfloat16& lo) {
    hi = __float2bfloat16(x);
    lo = __float2bfloat16(x - __bfloat162float(hi));
}

// ======================= plain GEMM (for xp): C = A @ Bw^T + bias =======================
__global__ void __launch_bounds__(256)
tc_gemm(const __nv_bfloat16* __restrict__ A, long lda,
        const __nv_bfloat16* __restrict__ Bw, long ldb, int K,
        const float* __restrict__ bias1,
        float* __restrict__ Cout, long ldc)
{
    extern __shared__ char smem[];
    const uint32_t sb = smem_u32(smem);
    const int tid  = threadIdx.x;
    const int wid  = tid >> 5;
    const int lane = tid & 31;
    const int wm   = wid >> 1;
    const int wn   = wid & 1;
    const long rowBase = (long)blockIdx.y * TM_;
    const long colBase = (long)blockIdx.x * TN_;
    const uint32_t abuf[2] = { sb + SM_A0, sb + SM_A1 };
    const uint32_t bbuf[2] = { sb + SM_B0, sb + SM_B1 };

    float acc[2][8][4];
#pragma unroll
    for (int i = 0; i < 2; i++)
#pragma unroll
        for (int j = 0; j < 8; j++)
#pragma unroll
            for (int k = 0; k < 4; k++) acc[i][j][k] = 0.f;

    const int nch = K / KC;

#define LOAD_CHUNK1(c, buf) do { \
    _Pragma("unroll") \
    for (int l = 0; l < 4; l++) { \
        int idx = tid + 256 * l; int r = idx >> 3, v = idx & 7; \
        const void* gp = A + (rowBase + r) * lda + (long)(c) * KC + v * 8; \
        uint32_t s = abuf[buf] + SWZ128(r * 128 + v * 16); \
        asm volatile("cp.async.cg.shared.global [%0], [%1], 16;\n" :: "r"(s), "l"(gp)); \
    } \
    _Pragma("unroll") \
    for (int l = 0; l < 4; l++) { \
        int idx = tid + 256 * l; int r = idx >> 3, v = idx & 7; \
        const void* gp = Bw + (colBase + r) * ldb + (long)(c) * KC + v * 8; \
        uint32_t s = bbuf[buf] + SWZ128(r * 128 + v * 16); \
        asm volatile("cp.async.cg.shared.global [%0], [%1], 16;\n" :: "r"(s), "l"(gp)); \
    } \
    asm volatile("cp.async.commit_group;\n"); \
} while (0)

    LOAD_CHUNK1(0, 0);
    if (nch > 1) LOAD_CHUNK1(1, 1);

    for (int c = 0; c < nch; c++) {
        const int buf = c & 1;
        if (c + 1 < nch) asm volatile("cp.async.wait_group 1;\n" ::: "memory");
        else             asm volatile("cp.async.wait_group 0;\n" ::: "memory");
        __syncthreads();
        const uint32_t As = abuf[buf], Bs = bbuf[buf];
#pragma unroll
        for (int ks = 0; ks < 4; ks++) {
            uint32_t afr[2][4];
#pragma unroll
            for (int mt = 0; mt < 2; mt++) {
                int row = wm * 32 + mt * 16 + (lane & 15);
                int kc  = ks * 16 + ((lane >> 4) << 3);
                ldsm_x4(afr[mt], As + SWZ128(row * 128 + kc * 2));
            }
            uint32_t bfr[4][4];
#pragma unroll
            for (int bt = 0; bt < 4; bt++) {
                int nr = wn * 64 + bt * 16 + (lane & 7) + ((lane >> 4) << 3);
                int kc = ks * 16 + (((lane >> 3) & 1) << 3);
                ldsm_x4(bfr[bt], Bs + SWZ128(nr * 128 + kc * 2));
            }
#pragma unroll
            for (int mt = 0; mt < 2; mt++)
#pragma unroll
                for (int nt = 0; nt < 8; nt++) {
                    const uint32_t* bp = bfr[nt >> 1];
                    if (nt & 1) mma_bf16(acc[mt][nt], afr[mt], bp[2], bp[3]);
                    else        mma_bf16(acc[mt][nt], afr[mt], bp[0], bp[1]);
                }
        }
        __syncthreads();
        if (c + 2 < nch) LOAD_CHUNK1(c + 2, buf);
    }

#pragma unroll
    for (int mt = 0; mt < 2; mt++)
#pragma unroll
        for (int nt = 0; nt < 8; nt++) {
            long row = rowBase + wm * 32 + mt * 16 + (lane >> 2);
            long col = colBase + wn * 64 + nt * 8 + ((lane & 3) << 1);
            float2 v0 = make_float2(acc[mt][nt][0], acc[mt][nt][1]);
            float2 v1 = make_float2(acc[mt][nt][2], acc[mt][nt][3]);
            if (bias1) {
                float2 b = *(const float2*)&bias1[col];
                v0.x += b.x; v0.y += b.y; v1.x += b.x; v1.y += b.y;
            }
            *(float2*)&Cout[row * ldc + col] = v0;
            *(float2*)&Cout[(row + 8) * ldc + col] = v1;
        }
}

// ======================= fused GEMM + LSTM cell =======================
// gates = [A1 | A2] @ Wc^T + biasF (gate-interleaved cols: n = unit*4 + gate)
// then c/h update; h written split (hi/hi/lo) into Wact+actOff; optional hs, hn, cn.
__global__ void __launch_bounds__(256)
gemm_lstm(const __nv_bfloat16* __restrict__ A1, long lda1, int nch1,
          const __nv_bfloat16* __restrict__ A2, long lda2, int nch2,
          const __nv_bfloat16* __restrict__ Wc,
          const float* __restrict__ biasF,
          float* __restrict__ cst,
          __nv_bfloat16* __restrict__ Wact, int actOff,
          float* __restrict__ hsp, int t,
          float* __restrict__ hnp, float* __restrict__ cnp)
{
    extern __shared__ char smem[];
    const uint32_t sb = smem_u32(smem);
    const int tid  = threadIdx.x;
    const int wid  = tid >> 5;
    const int lane = tid & 31;
    const int wm   = wid >> 1;
    const int wn   = wid & 1;
    const long rowBase = (long)blockIdx.y * TM_;
    const long colBase = (long)blockIdx.x * TN_;
    const uint32_t abuf[2] = { sb + SM_A0, sb + SM_A1 };
    const uint32_t bbuf[2] = { sb + SM_B0, sb + SM_B1 };

    float acc[2][8][4];
#pragma unroll
    for (int i = 0; i < 2; i++)
#pragma unroll
        for (int j = 0; j < 8; j++)
#pragma unroll
            for (int k = 0; k < 4; k++) acc[i][j][k] = 0.f;

    const int nch = nch1 + nch2;

#define LOAD_CHUNK2(c, buf) do { \
    const __nv_bfloat16* Asrc; long Alda; int cl; \
    if ((c) < nch1) { Asrc = A1; Alda = lda1; cl = (c); } \
    else            { Asrc = A2; Alda = lda2; cl = (c) - nch1; } \
    _Pragma("unroll") \
    for (int l = 0; l < 4; l++) { \
        int idx = tid + 256 * l; int r = idx >> 3, v = idx & 7; \
        const void* gp = Asrc + (rowBase + r) * Alda + (long)cl * KC + v * 8; \
        uint32_t s = abuf[buf] + SWZ128(r * 128 + v * 16); \
        asm volatile("cp.async.cg.shared.global [%0], [%1], 16;\n" :: "r"(s), "l"(gp)); \
    } \
    _Pragma("unroll") \
    for (int l = 0; l < 4; l++) { \
        int idx = tid + 256 * l; int r = idx >> 3, v = idx & 7; \
        const void* gp = Wc + (colBase + r) * (long)K6H + (long)(c) * KC + v * 8; \
        uint32_t s = bbuf[buf] + SWZ128(r * 128 + v * 16); \
        asm volatile("cp.async.cg.shared.global [%0], [%1], 16;\n" :: "r"(s), "l"(gp)); \
    } \
    asm volatile("cp.async.commit_group;\n"); \
} while (0)

    LOAD_CHUNK2(0, 0);
    if (nch > 1) LOAD_CHUNK2(1, 1);

    for (int c = 0; c < nch; c++) {
        const int buf = c & 1;
        if (c + 1 < nch) asm volatile("cp.async.wait_group 1;\n" ::: "memory");
        else             asm volatile("cp.async.wait_group 0;\n" ::: "memory");
        __syncthreads();
        const uint32_t As = abuf[buf], Bs = bbuf[buf];
#pragma unroll
        for (int ks = 0; ks < 4; ks++) {
            uint32_t afr[2][4];
#pragma unroll
            for (int mt = 0; mt < 2; mt++) {
                int row = wm * 32 + mt * 16 + (lane & 15);
                int kc  = ks * 16 + ((lane >> 4) << 3);
                ldsm_x4(afr[mt], As + SWZ128(row * 128 + kc * 2));
            }
            uint32_t bfr[4][4];
#pragma unroll
            for (int bt = 0; bt < 4; bt++) {
                int nr = wn * 64 + bt * 16 + (lane & 7) + ((lane >> 4) << 3);
                int kc = ks * 16 + (((lane >> 3) & 1) << 3);
                ldsm_x4(bfr[bt], Bs + SWZ128(nr * 128 + kc * 2));
            }
#pragma unroll
            for (int mt = 0; mt < 2; mt++)
#pragma unroll
                for (int nt = 0; nt < 8; nt++) {
                    const uint32_t* bp = bfr[nt >> 1];
                    if (nt & 1) mma_bf16(acc[mt][nt], afr[mt], bp[2], bp[3]);
                    else        mma_bf16(acc[mt][nt], afr[mt], bp[0], bp[1]);
                }
        }
        __syncthreads();
        if (c + 2 < nch) LOAD_CHUNK2(c + 2, buf);
    }

    // ---------- fused LSTM epilogue (2 halves of 64 cols = 16 units each) ----------
    __syncthreads();
    float* stage = (float*)smem;   // 128 x STAGE_LD floats
#pragma unroll 1
    for (int half = 0; half < 2; half++) {
        if (wn == half) {
#pragma unroll
            for (int mt = 0; mt < 2; mt++)
#pragma unroll
                for (int nt = 0; nt < 8; nt++) {
                    int row_l = wm * 32 + mt * 16 + (lane >> 2);
                    int col_l = nt * 8 + ((lane & 3) << 1);
                    *(float2*)&stage[row_l * STAGE_LD + col_l] =
                        make_float2(acc[mt][nt][0], acc[mt][nt][1]);
                    *(float2*)&stage[(row_l + 8) * STAGE_LD + col_l] =
                        make_float2(acc[mt][nt][2], acc[mt][nt][3]);
                }
        }
        __syncthreads();

        const int u_l = tid & 15;                 // unit within half
        const long u_g = colBase / 4 + half * 16 + u_l;   // global unit 0..255
        const float4 bv = *(const float4*)&biasF[u_g * 4];
#pragma unroll
        for (int rr = 0; rr < 8; rr++) {
            int row_l = (tid >> 4) + rr * 16;
            long b = rowBase + row_l;
            float4 gv = *(float4*)&stage[row_l * STAGE_LD + u_l * 4];
            float gi = gv.x + bv.x;
            float gf = gv.y + bv.y;
            float gg = gv.z + bv.z;
            float go = gv.w + bv.w;
            long cidx = b * H_ + u_g;
            float c_new = sigmoidf_(gf) * cst[cidx] + sigmoidf_(gi) * tanhf(gg);
            float h_new = sigmoidf_(go) * tanhf(c_new);
            cst[cidx] = c_new;
            __nv_bfloat16 hi, lo; split_bf16(h_new, hi, lo);
            __nv_bfloat16* a = Wact + b * K6H + actOff;
            a[u_g] = hi; a[u_g + 256] = hi; a[u_g + 512] = lo;
            if (hsp) hsp[(b * T_ + t) * H_ + u_g] = h_new;
            if (hnp) { hnp[cidx] = h_new; cnp[cidx] = c_new; }
        }
        __syncthreads();
    }
}

// ======================= prep kernels =======================
__global__ void zero_misc_kernel() {
    long n = (long)B_ * K6H;
    for (long i = blockIdx.x * (long)blockDim.x + threadIdx.x; i < n; i += (long)gridDim.x * blockDim.x) {
        g_ActA[i] = __float2bfloat16(0.f);
        g_ActB[i] = __float2bfloat16(0.f);
    }
    for (int i = blockIdx.x * blockDim.x + threadIdx.x; i < B_ * H_; i += gridDim.x * blockDim.x) {
        g_c0[i] = 0.f; g_c1[i] = 0.f;
    }
    for (int i = blockIdx.x * blockDim.x + threadIdx.x; i < H_ * (KX - 3 * F_); i += gridDim.x * blockDim.x) {
        int r = i / (KX - 3 * F_), c = i % (KX - 3 * F_);
        g_WbInp[(size_t)r * KX + 3 * F_ + c] = __float2bfloat16(0.f);
    }
}

__global__ void split_X_kernel(const float* __restrict__ X) {
    long n = (long)NBT * KX;
    for (long i = blockIdx.x * (long)blockDim.x + threadIdx.x; i < n; i += (long)gridDim.x * blockDim.x) {
        long row = i / KX; int col = (int)(i % KX);
        if (col >= 3 * F_) { g_Xsplit[i] = __float2bfloat16(0.f); continue; }
        int seg = col / F_, k = col % F_;
        float x = X[row * F_ + k];
        __nv_bfloat16 hi, lo; split_bf16(x, hi, lo);
        g_Xsplit[i] = (seg == 2) ? lo : hi;
    }
}

// W_inp [256,561] -> [hi | lo | hi] rows of g_WbInp
__global__ void split_Winp_kernel(const float* __restrict__ W) {
    int n = H_ * F_;
    for (int i = blockIdx.x * blockDim.x + threadIdx.x; i < n; i += gridDim.x * blockDim.x) {
        int r = i / F_, k = i % F_;
        __nv_bfloat16 hi, lo; split_bf16(W[i], hi, lo);
        __nv_bfloat16* o = g_WbInp + (size_t)r * KX;
        o[k] = hi; o[F_ + k] = lo; o[2 * F_ + k] = hi;
    }
}

// Build gate-interleaved split weights: dst row n = j*4+g  <-  src row r = g*256+j
// layout per row: [Wih hi|lo|hi (768) | Whh hi|lo|hi (768)]; fused bias.
__global__ void fuse_W_kernel(const float* __restrict__ Wih, const float* __restrict__ Whh,
                              const float* __restrict__ bih, const float* __restrict__ bhh,
                              __nv_bfloat16* __restrict__ Wc, float* __restrict__ biasF)
{
    int total = G4H * H_;
    for (int i = blockIdx.x * blockDim.x + threadIdx.x; i < total; i += gridDim.x * blockDim.x) {
        int n = i >> 8, k = i & 255;
        int j = n >> 2, g = n & 3;
        int r = g * 256 + j;
        __nv_bfloat16* row = Wc + (size_t)n * K6H;
        __nv_bfloat16 hi, lo;
        split_bf16(Wih[r * 256 + k], hi, lo);
        row[k] = hi; row[256 + k] = lo; row[512 + k] = hi;
        split_bf16(Whh[r * 256 + k], hi, lo);
        row[768 + k] = hi; row[1024 + k] = lo; row[1280 + k] = hi;
        if (k == 0) biasF[n] = bih[r] + bhh[r];
    }
}

__global__ void __launch_bounds__(256) split_xp_kernel() {
    long n = (long)NBT * H_;
    for (long i = blockIdx.x * (long)blockDim.x + threadIdx.x; i < n; i += (long)gridDim.x * blockDim.x) {
        long row = i >> 8; int j = (int)(i & 255);
        __nv_bfloat16 hi, lo; split_bf16(g_xp[i], hi, lo);
        __nv_bfloat16* o = g_Axp + row * K3H;
        o[j] = hi; o[j + 256] = hi; o[j + 512] = lo;
    }
}

__global__ void __launch_bounds__(256)
proj_kernel(const float* __restrict__ W_out, const float* __restrict__ b_out, float* __restrict__ out)
{
    __shared__ float Ws[O_ * H_];
    __shared__ float bs[O_];
    for (int i = threadIdx.x; i < O_ * H_; i += blockDim.x) Ws[i] = W_out[i];
    if (threadIdx.x < O_) bs[threadIdx.x] = b_out[threadIdx.x];
    __syncthreads();
    int warp = threadIdx.x / 32, lane = threadIdx.x % 32;
    long row = (long)blockIdx.x * 8 + warp;
    if (row >= NBT) return;
    float x[H_ / 32];
#pragma unroll
    for (int j = 0; j < H_ / 32; j++) x[j] = g_hs[row * H_ + lane + 32 * j];
#pragma unroll
    for (int o = 0; o < O_; o++) {
        float s = 0.f;
#pragma unroll
        for (int j = 0; j < H_ / 32; j++) s = fmaf(x[j], Ws[o * H_ + lane + 32 * j], s);
#pragma unroll
        for (int off = 16; off > 0; off >>= 1) s += __shfl_xor_sync(0xffffffffu, s, off);
        if (lane == 0) out[row * O_ + o] = s + bs[o];
    }
}

// ======================= launch =======================
extern "C" void kernel_launch(void* const* d_in, const int* in_sizes, int n_in,
                              void* d_out, int out_size)
{
    (void)in_sizes; (void)n_in; (void)out_size;
    const float* X     = (const float*)d_in[0];
    const float* W_inp = (const float*)d_in[1];
    const float* b_inp = (const float*)d_in[2];
    const float* Wih0  = (const float*)d_in[3];
    const float* Whh0  = (const float*)d_in[4];
    const float* bih0  = (const float*)d_in[5];
    const float* bhh0  = (const float*)d_in[6];
    const float* Wih1  = (const float*)d_in[7];
    const float* Whh1  = (const float*)d_in[8];
    const float* bih1  = (const float*)d_in[9];
    const float* bhh1  = (const float*)d_in[10];
    const float* W_out = (const float*)d_in[11];
    const float* b_out = (const float*)d_in[12];

    float* out     = (float*)d_out;
    float* hn_base = out + (size_t)B_ * T_ * O_;
    float* cn_base = hn_base + (size_t)2 * B_ * H_;

    static bool init = false;
    static __nv_bfloat16 *Xsplit, *Axp, *ActA, *ActB, *WbInp, *Wc0, *Wc1;
    static float *xp, *c0, *c1, *hs, *bias0, *bias1;
    if (!init) {
        cudaGetSymbolAddress((void**)&Xsplit, g_Xsplit);
        cudaGetSymbolAddress((void**)&Axp,    g_Axp);
        cudaGetSymbolAddress((void**)&ActA,   g_ActA);
        cudaGetSymbolAddress((void**)&ActB,   g_ActB);
        cudaGetSymbolAddress((void**)&WbInp,  g_WbInp);
        cudaGetSymbolAddress((void**)&Wc0,    g_Wc0);
        cudaGetSymbolAddress((void**)&Wc1,    g_Wc1);
        cudaGetSymbolAddress((void**)&xp,     g_xp);
        cudaGetSymbolAddress((void**)&c0,     g_c0);
        cudaGetSymbolAddress((void**)&c1,     g_c1);
        cudaGetSymbolAddress((void**)&hs,     g_hs);
        cudaGetSymbolAddress((void**)&bias0,  g_bias0);
        cudaGetSymbolAddress((void**)&bias1,  g_bias1);
        cudaFuncSetAttribute(tc_gemm,   cudaFuncAttributeMaxDynamicSharedMemorySize, SM_TOTAL);
        cudaFuncSetAttribute(gemm_lstm, cudaFuncAttributeMaxDynamicSharedMemorySize, SM_TOTAL);
        init = true;
    }

    // prep
    zero_misc_kernel<<<1024, 256>>>();
    split_X_kernel<<<2048, 256>>>(X);
    split_Winp_kernel<<<256, 256>>>(W_inp);
    fuse_W_kernel<<<512, 256>>>(Wih0, Whh0, bih0, bhh0, Wc0, bias0);
    fuse_W_kernel<<<512, 256>>>(Wih1, Whh1, bih1, bhh1, Wc1, bias1);

    // xp = X @ W_inp^T + b_inp
    {
        dim3 grid(H_ / TN_, NBT / TM_);   // (2, 640)
        tc_gemm<<<grid, 256, SM_TOTAL>>>(Xsplit, KX, WbInp, KX, KX, b_inp, xp, H_);
    }
    split_xp_kernel<<<2048, 256>>>();

    // recurrence: 2 fused GEMM+LSTM launches per step
    for (int t = 0; t < T_; t++) {
        bool last = (t == T_ - 1);
        __nv_bfloat16* Rbuf = (t & 1) ? ActB : ActA;
        __nv_bfloat16* Wbuf = (t & 1) ? ActA : ActB;
        dim3 grid(G4H / TN_, B_ / TM_);   // (8, 64)

        // layer0: gates = [xp_t | h0_old] @ Wc0^T + bias0
        gemm_lstm<<<grid, 256, SM_TOTAL>>>(
            Axp + (size_t)t * K3H, (long)T_ * K3H, K3H / KC,
            Rbuf, K6H, K3H / KC,
            Wc0, bias0, c0, Wbuf, 0,
            nullptr, t,
            last ? hn_base : nullptr, last ? cn_base : nullptr);

        // layer1: gates = [h0_new | h1_old] @ Wc1^T + bias1
        gemm_lstm<<<grid, 256, SM_TOTAL>>>(
            Wbuf, K6H, K3H / KC,
            Rbuf + K3H, K6H, K3H / KC,
            Wc1, bias1, c1, Wbuf, K3H,
            hs, t,
            last ? hn_base + (size_t)B_ * H_ : nullptr,
            last ? cn_base + (size_t)B_ * H_ : nullptr);
    }

    // outputs = hs @ W_out^T + b_out
    proj_kernel<<<NBT / 8, 256>>>(W_out, b_out, out);
}

// round 8
// speedup vs baseline: 1.2290x; 1.2290x over previous
#include <cuda_runtime.h>
#include <cuda_fp16.h>
#include <cstdint>
#include <math.h>

#define B_   8192
#define T_   10
#define F_   561
#define H_   256
#define O_   12
#define NBT  (B_ * T_)          // 81920
#define KXP  1152               // 2*561=1122 padded to 18*64
#define K2H  512                // 2*256
#define K4H  1024               // 4*256
#define G4H  1024

#define SWZ128(off) ((off) ^ (((off) >> 3) & 0x70))

__device__ __forceinline__ uint32_t smem_u32(const void* p) {
    uint32_t a;
    asm("{ .reg .u64 t; cvta.to.shared.u64 t, %1; cvt.u32.u64 %0, t; }" : "=r"(a) : "l"(p));
    return a;
}
__device__ __forceinline__ void ldsm_x4(uint32_t* r, uint32_t addr) {
    asm volatile("ldmatrix.sync.aligned.m8n8.x4.shared.b16 {%0,%1,%2,%3}, [%4];"
                 : "=r"(r[0]), "=r"(r[1]), "=r"(r[2]), "=r"(r[3]) : "r"(addr));
}
__device__ __forceinline__ void mma_f16(float* d, const uint32_t* a, uint32_t b0, uint32_t b1) {
    asm volatile("mma.sync.aligned.m16n8k16.row.col.f32.f16.f16.f32 "
                 "{%0,%1,%2,%3}, {%4,%5,%6,%7}, {%8,%9}, {%0,%1,%2,%3};"
                 : "+f"(d[0]), "+f"(d[1]), "+f"(d[2]), "+f"(d[3])
                 : "r"(a[0]), "r"(a[1]), "r"(a[2]), "r"(a[3]), "r"(b0), "r"(b1));
}

// ======================= scratch =======================
__device__ __half g_Xsplit[(size_t)NBT * KXP];      // [NBT,1152] = [Xhi(561)|Xlo(561)|pad]
__device__ __half g_Axp[(size_t)NBT * K2H];         // [NBT,512]  = [xphi|xplo]
__device__ __half g_ActA[(size_t)B_ * K4H];         // [B,1024]: [h0hi|h0lo|h1hi|h1lo]
__device__ __half g_ActB[(size_t)B_ * K4H];
__device__ float  g_c0[B_ * H_];
__device__ float  g_c1[B_ * H_];
__device__ float  g_hs[(size_t)NBT * H_];
__device__ __half g_WbInp[(size_t)H_ * KXP];        // [256,1152] = [Whi|Whi|pad]
__device__ __half g_Wc0[(size_t)G4H * K4H];         // gate-interleaved [Wih hi|Wih hi|Whh hi|Whh hi]
__device__ __half g_Wc1[(size_t)G4H * K4H];
__device__ float  g_bias0[G4H];
__device__ float  g_bias1[G4H];

// ======================= tile config =======================
#define TM_ 128
#define TN_ 128
#define KC  64
#define SM_A0  0
#define SM_A1  16384
#define SM_B0  32768
#define SM_B1  49152
#define SM_TOTAL 65536
#define STAGE_LD 72

__device__ __forceinline__ float sigmoidf_(float x) { return 1.0f / (1.0f + expf(-x)); }
__device__ __forceinline__ void split_f16(float x, __half& hi, __half& lo) {
    hi = __float2half_rn(x);
    lo = __float2half_rn(x - __half2float(hi));
}

// ======================= xp GEMM: Axp(hi/lo) = split(X @ W_inp^T + b) =======================
__global__ void __launch_bounds__(256)
xp_gemm(const __half* __restrict__ A, const __half* __restrict__ Bw,
        const float* __restrict__ bias, __half* __restrict__ Aout)
{
    extern __shared__ char smem[];
    const uint32_t sb = smem_u32(smem);
    const int tid  = threadIdx.x;
    const int wid  = tid >> 5;
    const int lane = tid & 31;
    const int wm   = wid >> 1;
    const int wn   = wid & 1;
    const long rowBase = (long)blockIdx.y * TM_;
    const long colBase = (long)blockIdx.x * TN_;
    const uint32_t abuf[2] = { sb + SM_A0, sb + SM_A1 };
    const uint32_t bbuf[2] = { sb + SM_B0, sb + SM_B1 };

    float acc[2][8][4];
#pragma unroll
    for (int i = 0; i < 2; i++)
#pragma unroll
        for (int j = 0; j < 8; j++)
#pragma unroll
            for (int k = 0; k < 4; k++) acc[i][j][k] = 0.f;

    const int nch = KXP / KC;   // 18

#define LOAD_CHUNK1(c, buf) do { \
    _Pragma("unroll") \
    for (int l = 0; l < 4; l++) { \
        int idx = tid + 256 * l; int r = idx >> 3, v = idx & 7; \
        const void* gp = A + (rowBase + r) * (long)KXP + (long)(c) * KC + v * 8; \
        uint32_t s = abuf[buf] + SWZ128(r * 128 + v * 16); \
        asm volatile("cp.async.cg.shared.global [%0], [%1], 16;\n" :: "r"(s), "l"(gp)); \
    } \
    _Pragma("unroll") \
    for (int l = 0; l < 4; l++) { \
        int idx = tid + 256 * l; int r = idx >> 3, v = idx & 7; \
        const void* gp = Bw + (colBase + r) * (long)KXP + (long)(c) * KC + v * 8; \
        uint32_t s = bbuf[buf] + SWZ128(r * 128 + v * 16); \
        asm volatile("cp.async.cg.shared.global [%0], [%1], 16;\n" :: "r"(s), "l"(gp)); \
    } \
    asm volatile("cp.async.commit_group;\n"); \
} while (0)

    LOAD_CHUNK1(0, 0);
    LOAD_CHUNK1(1, 1);

    for (int c = 0; c < nch; c++) {
        const int buf = c & 1;
        if (c + 1 < nch) asm volatile("cp.async.wait_group 1;\n" ::: "memory");
        else             asm volatile("cp.async.wait_group 0;\n" ::: "memory");
        __syncthreads();
        const uint32_t As = abuf[buf], Bs = bbuf[buf];
#pragma unroll
        for (int ks = 0; ks < 4; ks++) {
            uint32_t afr[2][4];
#pragma unroll
            for (int mt = 0; mt < 2; mt++) {
                int row = wm * 32 + mt * 16 + (lane & 15);
                int kc  = ks * 16 + ((lane >> 4) << 3);
                ldsm_x4(afr[mt], As + SWZ128(row * 128 + kc * 2));
            }
            uint32_t bfr[4][4];
#pragma unroll
            for (int bt = 0; bt < 4; bt++) {
                int nr = wn * 64 + bt * 16 + (lane & 7) + ((lane >> 4) << 3);
                int kc = ks * 16 + (((lane >> 3) & 1) << 3);
                ldsm_x4(bfr[bt], Bs + SWZ128(nr * 128 + kc * 2));
            }
#pragma unroll
            for (int mt = 0; mt < 2; mt++)
#pragma unroll
                for (int nt = 0; nt < 8; nt++) {
                    const uint32_t* bp = bfr[nt >> 1];
                    if (nt & 1) mma_f16(acc[mt][nt], afr[mt], bp[2], bp[3]);
                    else        mma_f16(acc[mt][nt], afr[mt], bp[0], bp[1]);
                }
        }
        __syncthreads();
        if (c + 2 < nch) LOAD_CHUNK1(c + 2, buf);
    }

    // epilogue: add bias, split to fp16 hi/lo, store into Axp [row*512 + col], [+256]
#pragma unroll
    for (int mt = 0; mt < 2; mt++)
#pragma unroll
        for (int nt = 0; nt < 8; nt++) {
            long row = rowBase + wm * 32 + mt * 16 + (lane >> 2);
            long col = colBase + wn * 64 + nt * 8 + ((lane & 3) << 1);
            float2 bv = *(const float2*)&bias[col];
#pragma unroll
            for (int h = 0; h < 2; h++) {
                long r2 = row + 8 * h;
                float vx = acc[mt][nt][2 * h + 0] + bv.x;
                float vy = acc[mt][nt][2 * h + 1] + bv.y;
                __half hx, lx, hy, ly;
                split_f16(vx, hx, lx);
                split_f16(vy, hy, ly);
                *(__half2*)&Aout[r2 * K2H + col]       = __halves2half2(hx, hy);
                *(__half2*)&Aout[r2 * K2H + 256 + col] = __halves2half2(lx, ly);
            }
        }
}

// ======================= fused GEMM + LSTM cell (1 or 2 jobs per launch) =======================
// job: gates = [A1(8 chunks, lda1) | A2(8 chunks, lda=1024)] @ Wc^T + biasF (gate-interleaved)
// then cell update; h written split (hi/lo fp16) into Wact+actOff; optional hs/hn/cn.
__global__ void __launch_bounds__(256)
gemm_lstm(const __half* A1a, long lda1a, const __half* A2a,
          const __half* Wca, const float* biasa, float* csta,
          __half* wacta, int woffa, float* hsa, int ta, float* hna, float* cna,
          const __half* A1b, long lda1b, const __half* A2b,
          const __half* Wcb, const float* biasb, float* cstb,
          __half* wactb, int woffb, float* hsb, int tb, float* hnb, float* cnb)
{
    const bool sec = (blockIdx.x >= 8);
    const __half* A1   = sec ? A1b : A1a;
    const long lda1    = sec ? lda1b : lda1a;
    const __half* A2   = sec ? A2b : A2a;
    const __half* Wc   = sec ? Wcb : Wca;
    const float* biasF = sec ? biasb : biasa;
    float* cst         = sec ? cstb : csta;
    __half* Wact       = sec ? wactb : wacta;
    const int actOff   = sec ? woffb : woffa;
    float* hsp         = sec ? hsb : hsa;
    const int t        = sec ? tb : ta;
    float* hnp         = sec ? hnb : hna;
    float* cnp         = sec ? cnb : cna;
    const int bx       = blockIdx.x & 7;

    extern __shared__ char smem[];
    const uint32_t sb = smem_u32(smem);
    const int tid  = threadIdx.x;
    const int wid  = tid >> 5;
    const int lane = tid & 31;
    const int wm   = wid >> 1;
    const int wn   = wid & 1;
    const long rowBase = (long)blockIdx.y * TM_;
    const long colBase = (long)bx * TN_;
    const uint32_t abuf[2] = { sb + SM_A0, sb + SM_A1 };
    const uint32_t bbuf[2] = { sb + SM_B0, sb + SM_B1 };

    float acc[2][8][4];
#pragma unroll
    for (int i = 0; i < 2; i++)
#pragma unroll
        for (int j = 0; j < 8; j++)
#pragma unroll
            for (int k = 0; k < 4; k++) acc[i][j][k] = 0.f;

#define NCH2 16

#define LOAD_CHUNK2(c, buf) do { \
    const __half* Asrc; long Alda; int cl; \
    if ((c) < 8) { Asrc = A1; Alda = lda1; cl = (c); } \
    else         { Asrc = A2; Alda = K4H;  cl = (c) - 8; } \
    _Pragma("unroll") \
    for (int l = 0; l < 4; l++) { \
        int idx = tid + 256 * l; int r = idx >> 3, v = idx & 7; \
        const void* gp = Asrc + (rowBase + r) * Alda + (long)cl * KC + v * 8; \
        uint32_t s = abuf[buf] + SWZ128(r * 128 + v * 16); \
        asm volatile("cp.async.cg.shared.global [%0], [%1], 16;\n" :: "r"(s), "l"(gp)); \
    } \
    _Pragma("unroll") \
    for (int l = 0; l < 4; l++) { \
        int idx = tid + 256 * l; int r = idx >> 3, v = idx & 7; \
        const void* gp = Wc + (colBase + r) * (long)K4H + (long)(c) * KC + v * 8; \
        uint32_t s = bbuf[buf] + SWZ128(r * 128 + v * 16); \
        asm volatile("cp.async.cg.shared.global [%0], [%1], 16;\n" :: "r"(s), "l"(gp)); \
    } \
    asm volatile("cp.async.commit_group;\n"); \
} while (0)

    LOAD_CHUNK2(0, 0);
    LOAD_CHUNK2(1, 1);

    for (int c = 0; c < NCH2; c++) {
        const int buf = c & 1;
        if (c + 1 < NCH2) asm volatile("cp.async.wait_group 1;\n" ::: "memory");
        else              asm volatile("cp.async.wait_group 0;\n" ::: "memory");
        __syncthreads();
        const uint32_t As = abuf[buf], Bs = bbuf[buf];
#pragma unroll
        for (int ks = 0; ks < 4; ks++) {
            uint32_t afr[2][4];
#pragma unroll
            for (int mt = 0; mt < 2; mt++) {
                int row = wm * 32 + mt * 16 + (lane & 15);
                int kc  = ks * 16 + ((lane >> 4) << 3);
                ldsm_x4(afr[mt], As + SWZ128(row * 128 + kc * 2));
            }
            uint32_t bfr[4][4];
#pragma unroll
            for (int bt = 0; bt < 4; bt++) {
                int nr = wn * 64 + bt * 16 + (lane & 7) + ((lane >> 4) << 3);
                int kc = ks * 16 + (((lane >> 3) & 1) << 3);
                ldsm_x4(bfr[bt], Bs + SWZ128(nr * 128 + kc * 2));
            }
#pragma unroll
            for (int mt = 0; mt < 2; mt++)
#pragma unroll
                for (int nt = 0; nt < 8; nt++) {
                    const uint32_t* bp = bfr[nt >> 1];
                    if (nt & 1) mma_f16(acc[mt][nt], afr[mt], bp[2], bp[3]);
                    else        mma_f16(acc[mt][nt], afr[mt], bp[0], bp[1]);
                }
        }
        __syncthreads();
        if (c + 2 < NCH2) LOAD_CHUNK2(c + 2, buf);
    }

    // ---------- fused LSTM epilogue ----------
    __syncthreads();
    float* stage = (float*)smem;   // 128 x STAGE_LD floats
#pragma unroll 1
    for (int half = 0; half < 2; half++) {
        if (wn == half) {
#pragma unroll
            for (int mt = 0; mt < 2; mt++)
#pragma unroll
                for (int nt = 0; nt < 8; nt++) {
                    int row_l = wm * 32 + mt * 16 + (lane >> 2);
                    int col_l = nt * 8 + ((lane & 3) << 1);
                    *(float2*)&stage[row_l * STAGE_LD + col_l] =
                        make_float2(acc[mt][nt][0], acc[mt][nt][1]);
                    *(float2*)&stage[(row_l + 8) * STAGE_LD + col_l] =
                        make_float2(acc[mt][nt][2], acc[mt][nt][3]);
                }
        }
        __syncthreads();

        const int u_l = tid & 15;
        const long u_g = (long)bx * 32 + half * 16 + u_l;   // global unit 0..255
        const float4 bv = *(const float4*)&biasF[u_g * 4];
#pragma unroll
        for (int rr = 0; rr < 8; rr++) {
            int row_l = (tid >> 4) + rr * 16;
            long b = rowBase + row_l;
            float4 gv = *(float4*)&stage[row_l * STAGE_LD + u_l * 4];
            float gi = gv.x + bv.x;
            float gf = gv.y + bv.y;
            float gg = gv.z + bv.z;
            float go = gv.w + bv.w;
            long cidx = b * H_ + u_g;
            float c_new = sigmoidf_(gf) * cst[cidx] + sigmoidf_(gi) * tanhf(gg);
            float h_new = sigmoidf_(go) * tanhf(c_new);
            cst[cidx] = c_new;
            __half hi, lo; split_f16(h_new, hi, lo);
            __half* a = Wact + b * K4H + actOff;
            a[u_g] = hi; a[u_g + 256] = lo;
            if (hsp) hsp[(b * T_ + t) * H_ + u_g] = h_new;
            if (hnp) { hnp[cidx] = h_new; cnp[cidx] = c_new; }
        }
        __syncthreads();
    }
}

// ======================= prep kernels =======================
__global__ void zero_misc_kernel() {
    long n = (long)B_ * K4H;
    for (long i = blockIdx.x * (long)blockDim.x + threadIdx.x; i < n; i += (long)gridDim.x * blockDim.x) {
        g_ActA[i] = __float2half(0.f);
        g_ActB[i] = __float2half(0.f);
    }
    for (int i = blockIdx.x * blockDim.x + threadIdx.x; i < B_ * H_; i += gridDim.x * blockDim.x) {
        g_c0[i] = 0.f; g_c1[i] = 0.f;
    }
    for (int i = blockIdx.x * blockDim.x + threadIdx.x; i < H_ * (KXP - 2 * F_); i += gridDim.x * blockDim.x) {
        int r = i / (KXP - 2 * F_), c = i % (KXP - 2 * F_);
        g_WbInp[(size_t)r * KXP + 2 * F_ + c] = __float2half(0.f);
    }
}

__global__ void split_X_kernel(const float* __restrict__ X) {
    long n = (long)NBT * KXP;
    for (long i = blockIdx.x * (long)blockDim.x + threadIdx.x; i < n; i += (long)gridDim.x * blockDim.x) {
        long row = i / KXP; int col = (int)(i % KXP);
        if (col >= 2 * F_) { g_Xsplit[i] = __float2half(0.f); continue; }
        int seg = col / F_, k = col % F_;
        float x = X[row * F_ + k];
        __half hi, lo; split_f16(x, hi, lo);
        g_Xsplit[i] = seg ? lo : hi;
    }
}

// W_inp [256,561] -> rows [Whi | Whi | pad]
__global__ void split_Winp_kernel(const float* __restrict__ W) {
    int n = H_ * F_;
    for (int i = blockIdx.x * blockDim.x + threadIdx.x; i < n; i += gridDim.x * blockDim.x) {
        int r = i / F_, k = i % F_;
        __half hi = __float2half_rn(W[i]);
        __half* o = g_WbInp + (size_t)r * KXP;
        o[k] = hi; o[F_ + k] = hi;
    }
}

// Gate-interleaved fp16 weights: dst row n = j*4+g <- src row r = g*256+j.
// Row layout (1024): [Wih hi | Wih hi | Whh hi | Whh hi]; fused bias.
__global__ void fuse_W_kernel(const float* __restrict__ Wih, const float* __restrict__ Whh,
                              const float* __restrict__ bih, const float* __restrict__ bhh,
                              __half* __restrict__ Wc, float* __restrict__ biasF)
{
    int total = G4H * H_;
    for (int i = blockIdx.x * blockDim.x + threadIdx.x; i < total; i += gridDim.x * blockDim.x) {
        int n = i >> 8, k = i & 255;
        int j = n >> 2, g = n & 3;
        int r = g * 256 + j;
        __half* row = Wc + (size_t)n * K4H;
        __half wi = __float2half_rn(Wih[r * 256 + k]);
        __half wh = __float2half_rn(Whh[r * 256 + k]);
        row[k] = wi; row[256 + k] = wi;
        row[512 + k] = wh; row[768 + k] = wh;
        if (k == 0) biasF[n] = bih[r] + bhh[r];
    }
}

__global__ void __launch_bounds__(256)
proj_kernel(const float* __restrict__ W_out, const float* __restrict__ b_out, float* __restrict__ out)
{
    __shared__ float Ws[O_ * H_];
    __shared__ float bs[O_];
    for (int i = threadIdx.x; i < O_ * H_; i += blockDim.x) Ws[i] = W_out[i];
    if (threadIdx.x < O_) bs[threadIdx.x] = b_out[threadIdx.x];
    __syncthreads();
    int warp = threadIdx.x / 32, lane = threadIdx.x % 32;
    long row = (long)blockIdx.x * 8 + warp;
    if (row >= NBT) return;
    float x[H_ / 32];
#pragma unroll
    for (int j = 0; j < H_ / 32; j++) x[j] = g_hs[row * H_ + lane + 32 * j];
#pragma unroll
    for (int o = 0; o < O_; o++) {
        float s = 0.f;
#pragma unroll
        for (int j = 0; j < H_ / 32; j++) s = fmaf(x[j], Ws[o * H_ + lane + 32 * j], s);
#pragma unroll
        for (int off = 16; off > 0; off >>= 1) s += __shfl_xor_sync(0xffffffffu, s, off);
        if (lane == 0) out[row * O_ + o] = s + bs[o];
    }
}

// ======================= launch =======================
extern "C" void kernel_launch(void* const* d_in, const int* in_sizes, int n_in,
                              void* d_out, int out_size)
{
    (void)in_sizes; (void)n_in; (void)out_size;
    const float* X     = (const float*)d_in[0];
    const float* W_inp = (const float*)d_in[1];
    const float* b_inp = (const float*)d_in[2];
    const float* Wih0  = (const float*)d_in[3];
    const float* Whh0  = (const float*)d_in[4];
    const float* bih0  = (const float*)d_in[5];
    const float* bhh0  = (const float*)d_in[6];
    const float* Wih1  = (const float*)d_in[7];
    const float* Whh1  = (const float*)d_in[8];
    const float* bih1  = (const float*)d_in[9];
    const float* bhh1  = (const float*)d_in[10];
    const float* W_out = (const float*)d_in[11];
    const float* b_out = (const float*)d_in[12];

    float* out     = (float*)d_out;
    float* hn_base = out + (size_t)B_ * T_ * O_;
    float* cn_base = hn_base + (size_t)2 * B_ * H_;

    static bool init = false;
    static __half *Xsplit, *Axp, *ActA, *ActB, *WbInp, *Wc0, *Wc1;
    static float *c0, *c1, *hs, *bias0, *bias1;
    if (!init) {
        cudaGetSymbolAddress((void**)&Xsplit, g_Xsplit);
        cudaGetSymbolAddress((void**)&Axp,    g_Axp);
        cudaGetSymbolAddress((void**)&ActA,   g_ActA);
        cudaGetSymbolAddress((void**)&ActB,   g_ActB);
        cudaGetSymbolAddress((void**)&WbInp,  g_WbInp);
        cudaGetSymbolAddress((void**)&Wc0,    g_Wc0);
        cudaGetSymbolAddress((void**)&Wc1,    g_Wc1);
        cudaGetSymbolAddress((void**)&c0,     g_c0);
        cudaGetSymbolAddress((void**)&c1,     g_c1);
        cudaGetSymbolAddress((void**)&hs,     g_hs);
        cudaGetSymbolAddress((void**)&bias0,  g_bias0);
        cudaGetSymbolAddress((void**)&bias1,  g_bias1);
        cudaFuncSetAttribute(xp_gemm,   cudaFuncAttributeMaxDynamicSharedMemorySize, SM_TOTAL);
        cudaFuncSetAttribute(gemm_lstm, cudaFuncAttributeMaxDynamicSharedMemorySize, SM_TOTAL);
        init = true;
    }

    // prep
    zero_misc_kernel<<<1024, 256>>>();
    split_X_kernel<<<2048, 256>>>(X);
    split_Winp_kernel<<<256, 256>>>(W_inp);
    fuse_W_kernel<<<512, 256>>>(Wih0, Whh0, bih0, bhh0, Wc0, bias0);
    fuse_W_kernel<<<512, 256>>>(Wih1, Whh1, bih1, bhh1, Wc1, bias1);

    // xp (fused split into epilogue): Axp = split(X @ W_inp^T + b_inp)
    {
        dim3 grid(H_ / TN_, NBT / TM_);   // (2, 640)
        xp_gemm<<<grid, 256, SM_TOTAL>>>(Xsplit, WbInp, b_inp, Axp);
    }

    // Recurrence, software-pipelined across the step boundary:
    //   P:      layer0(0)                       reads buf0(zeros), writes buf1
    //   L_i:    [layer1(i-1), layer0(i)] i=1..9 reads bufW_{i-1},  writes other
    //   F:      layer1(9)                       reads bufW_9
    // bufW_0 = ActB; bufW_i alternates.
    {
        dim3 g1(8, 64);
        // P: layer0(0)
        gemm_lstm<<<g1, 256, SM_TOTAL>>>(
            Axp, (long)T_ * K2H, ActA,          // A1=xp(0), A2=h0init(=0, ActA)
            Wc0, bias0, c0, ActB, 0,            // write h0(0) -> ActB
            nullptr, 0, nullptr, nullptr,
            // job1 = same (unused; grid.x=8)
            Axp, (long)T_ * K2H, ActA, Wc0, bias0, c0, ActB, 0,
            nullptr, 0, nullptr, nullptr);

        for (int i = 1; i <= 9; i++) {
            __half* bufR = ((i - 1) % 2 == 0) ? ActB : ActA;  // bufW_{i-1}
            __half* bufW = ((i - 1) % 2 == 0) ? ActA : ActB;
            int t1 = i - 1;       // layer1 step
            int t0 = i;           // layer0 step
            bool l0last = (t0 == T_ - 1);
            dim3 g2(16, 64);
            gemm_lstm<<<g2, 256, SM_TOTAL>>>(
                // job0: layer1(t1) = [h0(t1) | h1(t1-1)] @ Wc1
                bufR, (long)K4H, bufR + K2H,
                Wc1, bias1, c1, bufW, K2H,
                hs, t1, nullptr, nullptr,
                // job1: layer0(t0) = [xp(t0) | h0(t0-1)] @ Wc0
                Axp + (size_t)t0 * K2H, (long)T_ * K2H, bufR,
                Wc0, bias0, c0, bufW, 0,
                nullptr, t0,
                l0last ? hn_base : nullptr, l0last ? cn_base : nullptr);
        }

        // F: layer1(9); bufW_9 = ActA (i=9: (9-1)%2==0 -> writes ActA)
        __half* bufR = ActA;
        gemm_lstm<<<g1, 256, SM_TOTAL>>>(
            bufR, (long)K4H, bufR + K2H,
            Wc1, bias1, c1, ActB, K2H,          // write target unused afterwards
            hs, T_ - 1, hn_base + (size_t)B_ * H_, cn_base + (size_t)B_ * H_,
            bufR, (long)K4H, bufR + K2H, Wc1, bias1, c1, ActB, K2H,
            hs, T_ - 1, nullptr, nullptr);
    }

    // outputs = hs @ W_out^T + b_out
    proj_kernel<<<NBT / 8, 256>>>(W_out, b_out, out);
}

// round 12
// speedup vs baseline: 1.6311x; 1.3272x over previous
#include <cuda_runtime.h>
#include <cuda_fp16.h>
#include <cstdint>
#include <math.h>

#define B_   8192
#define T_   10
#define F_   561
#define H_   256
#define O_   12
#define NBT  (B_ * T_)          // 81920
#define KXS  576                // 561 padded to 9*64 (single-term X)
#define AXPW 256                // xp stored as single fp16 segment
#define K4H  1024               // Act row: [h0hi|h0lo|h1hi|h1lo]
#define KW   768                // recurrent weight row: [W_in | W_hh | W_hh]
#define G4H  1024

#define SWZ128(off) ((off) ^ (((off) >> 3) & 0x70))

__device__ __forceinline__ uint32_t smem_u32(const void* p) {
    uint32_t a;
    asm("{ .reg .u64 t; cvta.to.shared.u64 t, %1; cvt.u32.u64 %0, t; }" : "=r"(a) : "l"(p));
    return a;
}
__device__ __forceinline__ void ldsm_x4(uint32_t* r, uint32_t addr) {
    asm volatile("ldmatrix.sync.aligned.m8n8.x4.shared.b16 {%0,%1,%2,%3}, [%4];"
                 : "=r"(r[0]), "=r"(r[1]), "=r"(r[2]), "=r"(r[3]) : "r"(addr));
}
__device__ __forceinline__ void mma_f16(float* d, const uint32_t* a, uint32_t b0, uint32_t b1) {
    asm volatile("mma.sync.aligned.m16n8k16.row.col.f32.f16.f16.f32 "
                 "{%0,%1,%2,%3}, {%4,%5,%6,%7}, {%8,%9}, {%0,%1,%2,%3};"
                 : "+f"(d[0]), "+f"(d[1]), "+f"(d[2]), "+f"(d[3])
                 : "r"(a[0]), "r"(a[1]), "r"(a[2]), "r"(a[3]), "r"(b0), "r"(b1));
}

// ======================= scratch =======================
__device__ __half g_Xh[(size_t)NBT * KXS];          // [NBT,576] = [Xhi(561)|pad]
__device__ __half g_Axp[(size_t)NBT * AXPW];        // [NBT,256] fp16 xp
__device__ __half g_ActA[(size_t)B_ * K4H];         // [B,1024]: [h0hi|h0lo|h1hi|h1lo]
__device__ __half g_ActB[(size_t)B_ * K4H];
__device__ float  g_c0[B_ * H_];
__device__ float  g_c1[B_ * H_];
__device__ float  g_hs[(size_t)NBT * H_];
__device__ __half g_WbInp[(size_t)H_ * KXS];        // [256,576] = [Whi|pad]
__device__ __half g_Wc0[(size_t)G4H * KW];          // gate-interleaved [Wih0|Whh0|Whh0]
__device__ __half g_Wc1[(size_t)G4H * KW];          // gate-interleaved [Wih1|Whh1|Whh1]
__device__ float  g_bias0[G4H];
__device__ float  g_bias1[G4H];

// ======================= tile config =======================
#define TM_ 128
#define TN_ 128
#define KC  64
#define SM_A0  0
#define SM_A1  16384
#define SM_B0  32768
#define SM_B1  49152
#define SM_TOTAL 65536
#define STAGE_LD 72

__device__ __forceinline__ float sigmoidf_(float x) { return 1.0f / (1.0f + __expf(-x)); }
__device__ __forceinline__ void split_f16(float x, __half& hi, __half& lo) {
    hi = __float2half_rn(x);
    lo = __float2half_rn(x - __half2float(hi));
}

// ======================= xp GEMM: Axp = fp16(X @ W_inp^T + b) =======================
__global__ void __launch_bounds__(256)
xp_gemm(const __half* __restrict__ A, const __half* __restrict__ Bw,
        const float* __restrict__ bias, __half* __restrict__ Aout)
{
    extern __shared__ char smem[];
    const uint32_t sb = smem_u32(smem);
    const int tid  = threadIdx.x;
    const int wid  = tid >> 5;
    const int lane = tid & 31;
    const int wm   = wid >> 1;
    const int wn   = wid & 1;
    const long rowBase = (long)blockIdx.y * TM_;
    const long colBase = (long)blockIdx.x * TN_;
    const uint32_t abuf[2] = { sb + SM_A0, sb + SM_A1 };
    const uint32_t bbuf[2] = { sb + SM_B0, sb + SM_B1 };

    float acc[2][8][4];
#pragma unroll
    for (int i = 0; i < 2; i++)
#pragma unroll
        for (int j = 0; j < 8; j++)
#pragma unroll
            for (int k = 0; k < 4; k++) acc[i][j][k] = 0.f;

    const int nch = KXS / KC;   // 9

#define LOAD_CHUNK1(c, buf) do { \
    _Pragma("unroll") \
    for (int l = 0; l < 4; l++) { \
        int idx = tid + 256 * l; int r = idx >> 3, v = idx & 7; \
        const void* gp = A + (rowBase + r) * (long)KXS + (long)(c) * KC + v * 8; \
        uint32_t s = abuf[buf] + SWZ128(r * 128 + v * 16); \
        asm volatile("cp.async.cg.shared.global [%0], [%1], 16;\n" :: "r"(s), "l"(gp)); \
    } \
    _Pragma("unroll") \
    for (int l = 0; l < 4; l++) { \
        int idx = tid + 256 * l; int r = idx >> 3, v = idx & 7; \
        const void* gp = Bw + (colBase + r) * (long)KXS + (long)(c) * KC + v * 8; \
        uint32_t s = bbuf[buf] + SWZ128(r * 128 + v * 16); \
        asm volatile("cp.async.cg.shared.global [%0], [%1], 16;\n" :: "r"(s), "l"(gp)); \
    } \
    asm volatile("cp.async.commit_group;\n"); \
} while (0)

    LOAD_CHUNK1(0, 0);
    LOAD_CHUNK1(1, 1);

    for (int c = 0; c < nch; c++) {
        const int buf = c & 1;
        if (c + 1 < nch) asm volatile("cp.async.wait_group 1;\n" ::: "memory");
        else             asm volatile("cp.async.wait_group 0;\n" ::: "memory");
        __syncthreads();
        const uint32_t As = abuf[buf], Bs = bbuf[buf];
#pragma unroll
        for (int ks = 0; ks < 4; ks++) {
            uint32_t afr[2][4];
#pragma unroll
            for (int mt = 0; mt < 2; mt++) {
                int row = wm * 32 + mt * 16 + (lane & 15);
                int kc  = ks * 16 + ((lane >> 4) << 3);
                ldsm_x4(afr[mt], As + SWZ128(row * 128 + kc * 2));
            }
            uint32_t bfr[4][4];
#pragma unroll
            for (int bt = 0; bt < 4; bt++) {
                int nr = wn * 64 + bt * 16 + (lane & 7) + ((lane >> 4) << 3);
                int kc = ks * 16 + (((lane >> 3) & 1) << 3);
                ldsm_x4(bfr[bt], Bs + SWZ128(nr * 128 + kc * 2));
            }
#pragma unroll
            for (int mt = 0; mt < 2; mt++)
#pragma unroll
                for (int nt = 0; nt < 8; nt++) {
                    const uint32_t* bp = bfr[nt >> 1];
                    if (nt & 1) mma_f16(acc[mt][nt], afr[mt], bp[2], bp[3]);
                    else        mma_f16(acc[mt][nt], afr[mt], bp[0], bp[1]);
                }
        }
        __syncthreads();
        if (c + 2 < nch) LOAD_CHUNK1(c + 2, buf);
    }

    // epilogue: add bias, round to fp16, store
#pragma unroll
    for (int mt = 0; mt < 2; mt++)
#pragma unroll
        for (int nt = 0; nt < 8; nt++) {
            long row = rowBase + wm * 32 + mt * 16 + (lane >> 2);
            long col = colBase + wn * 64 + nt * 8 + ((lane & 3) << 1);
            float2 bv = *(const float2*)&bias[col];
#pragma unroll
            for (int h = 0; h < 2; h++) {
                long r2 = row + 8 * h;
                float vx = acc[mt][nt][2 * h + 0] + bv.x;
                float vy = acc[mt][nt][2 * h + 1] + bv.y;
                *(__half2*)&Aout[r2 * AXPW + col] =
                    __halves2half2(__float2half_rn(vx), __float2half_rn(vy));
            }
        }
}

// ======================= fused GEMM + LSTM cell (2 jobs per launch) =======================
// job: gates = [A1 (4 chunks, lda1) | A2 (8 chunks, lda=1024)] @ Wc^T + biasF
//      (gate-interleaved cols n = unit*4 + gate), then cell update.
// h written split (hi/lo fp16) into Wact+actOff; optional hs/hn/cn.
#define NCH2 12

__global__ void __launch_bounds__(256)
gemm_lstm(const __half* A1a, long lda1a, const __half* A2a,
          const __half* Wca, const float* biasa, float* csta,
          __half* wacta, int woffa, float* hsa, int ta, float* hna, float* cna,
          const __half* A1b, long lda1b, const __half* A2b,
          const __half* Wcb, const float* biasb, float* cstb,
          __half* wactb, int woffb, float* hsb, int tb, float* hnb, float* cnb)
{
    const bool sec = (blockIdx.x >= 8);
    const __half* A1   = sec ? A1b : A1a;
    const long lda1    = sec ? lda1b : lda1a;
    const __half* A2   = sec ? A2b : A2a;
    const __half* Wc   = sec ? Wcb : Wca;
    const float* biasF = sec ? biasb : biasa;
    float* cst         = sec ? cstb : csta;
    __half* Wact       = sec ? wactb : wacta;
    const int actOff   = sec ? woffb : woffa;
    float* hsp         = sec ? hsb : hsa;
    const int t        = sec ? tb : ta;
    float* hnp         = sec ? hnb : hna;
    float* cnp         = sec ? cnb : cna;
    const int bx       = blockIdx.x & 7;

    extern __shared__ char smem[];
    const uint32_t sb = smem_u32(smem);
    const int tid  = threadIdx.x;
    const int wid  = tid >> 5;
    const int lane = tid & 31;
    const int wm   = wid >> 1;
    const int wn   = wid & 1;
    const long rowBase = (long)blockIdx.y * TM_;
    const long colBase = (long)bx * TN_;
    const uint32_t abuf[2] = { sb + SM_A0, sb + SM_A1 };
    const uint32_t bbuf[2] = { sb + SM_B0, sb + SM_B1 };

    float acc[2][8][4];
#pragma unroll
    for (int i = 0; i < 2; i++)
#pragma unroll
        for (int j = 0; j < 8; j++)
#pragma unroll
            for (int k = 0; k < 4; k++) acc[i][j][k] = 0.f;

#define LOAD_CHUNK2(c, buf) do { \
    const __half* Asrc; long Alda; int cl; \
    if ((c) < 4) { Asrc = A1; Alda = lda1; cl = (c); } \
    else         { Asrc = A2; Alda = K4H;  cl = (c) - 4; } \
    _Pragma("unroll") \
    for (int l = 0; l < 4; l++) { \
        int idx = tid + 256 * l; int r = idx >> 3, v = idx & 7; \
        const void* gp = Asrc + (rowBase + r) * Alda + (long)cl * KC + v * 8; \
        uint32_t s = abuf[buf] + SWZ128(r * 128 + v * 16); \
        asm volatile("cp.async.cg.shared.global [%0], [%1], 16;\n" :: "r"(s), "l"(gp)); \
    } \
    _Pragma("unroll") \
    for (int l = 0; l < 4; l++) { \
        int idx = tid + 256 * l; int r = idx >> 3, v = idx & 7; \
        const void* gp = Wc + (colBase + r) * (long)KW + (long)(c) * KC + v * 8; \
        uint32_t s = bbuf[buf] + SWZ128(r * 128 + v * 16); \
        asm volatile("cp.async.cg.shared.global [%0], [%1], 16;\n" :: "r"(s), "l"(gp)); \
    } \
    asm volatile("cp.async.commit_group;\n"); \
} while (0)

    LOAD_CHUNK2(0, 0);
    LOAD_CHUNK2(1, 1);

    for (int c = 0; c < NCH2; c++) {
        const int buf = c & 1;
        if (c + 1 < NCH2) asm volatile("cp.async.wait_group 1;\n" ::: "memory");
        else              asm volatile("cp.async.wait_group 0;\n" ::: "memory");
        __syncthreads();
        const uint32_t As = abuf[buf], Bs = bbuf[buf];
#pragma unroll
        for (int ks = 0; ks < 4; ks++) {
            uint32_t afr[2][4];
#pragma unroll
            for (int mt = 0; mt < 2; mt++) {
                int row = wm * 32 + mt * 16 + (lane & 15);
                int kc  = ks * 16 + ((lane >> 4) << 3);
                ldsm_x4(afr[mt], As + SWZ128(row * 128 + kc * 2));
            }
            uint32_t bfr[4][4];
#pragma unroll
            for (int bt = 0; bt < 4; bt++) {
                int nr = wn * 64 + bt * 16 + (lane & 7) + ((lane >> 4) << 3);
                int kc = ks * 16 + (((lane >> 3) & 1) << 3);
                ldsm_x4(bfr[bt], Bs + SWZ128(nr * 128 + kc * 2));
            }
#pragma unroll
            for (int mt = 0; mt < 2; mt++)
#pragma unroll
                for (int nt = 0; nt < 8; nt++) {
                    const uint32_t* bp = bfr[nt >> 1];
                    if (nt & 1) mma_f16(acc[mt][nt], afr[mt], bp[2], bp[3]);
                    else        mma_f16(acc[mt][nt], afr[mt], bp[0], bp[1]);
                }
        }
        __syncthreads();
        if (c + 2 < NCH2) LOAD_CHUNK2(c + 2, buf);
    }

    // ---------- fused LSTM epilogue ----------
    __syncthreads();
    float* stage = (float*)smem;   // 128 x STAGE_LD floats
#pragma unroll 1
    for (int half = 0; half < 2; half++) {
        if (wn == half) {
#pragma unroll
            for (int mt = 0; mt < 2; mt++)
#pragma unroll
                for (int nt = 0; nt < 8; nt++) {
                    int row_l = wm * 32 + mt * 16 + (lane >> 2);
                    int col_l = nt * 8 + ((lane & 3) << 1);
                    *(float2*)&stage[row_l * STAGE_LD + col_l] =
                        make_float2(acc[mt][nt][0], acc[mt][nt][1]);
                    *(float2*)&stage[(row_l + 8) * STAGE_LD + col_l] =
                        make_float2(acc[mt][nt][2], acc[mt][nt][3]);
                }
        }
        __syncthreads();

        const int u_l = tid & 15;
        const long u_g = (long)bx * 32 + half * 16 + u_l;   // global unit 0..255
        const float4 bv = *(const float4*)&biasF[u_g * 4];
#pragma unroll
        for (int rr = 0; rr < 8; rr++) {
            int row_l = (tid >> 4) + rr * 16;
            long b = rowBase + row_l;
            float4 gv = *(float4*)&stage[row_l * STAGE_LD + u_l * 4];
            float gi = gv.x + bv.x;
            float gf = gv.y + bv.y;
            float gg = gv.z + bv.z;
            float go = gv.w + bv.w;
            long cidx = b * H_ + u_g;
            float c_new = sigmoidf_(gf) * cst[cidx] + sigmoidf_(gi) * tanhf(gg);
            float h_new = sigmoidf_(go) * tanhf(c_new);
            cst[cidx] = c_new;
            __half hi, lo; split_f16(h_new, hi, lo);
            __half* a = Wact + b * K4H + actOff;
            a[u_g] = hi; a[u_g + 256] = lo;
            if (hsp) hsp[(b * T_ + t) * H_ + u_g] = h_new;
            if (hnp) { hnp[cidx] = h_new; cnp[cidx] = c_new; }
        }
        __syncthreads();
    }
}

// ======================= prep kernels =======================
__global__ void zero_misc_kernel() {
    long n = (long)B_ * K4H;
    for (long i = blockIdx.x * (long)blockDim.x + threadIdx.x; i < n; i += (long)gridDim.x * blockDim.x) {
        g_ActA[i] = __float2half(0.f);
        g_ActB[i] = __float2half(0.f);
    }
    for (int i = blockIdx.x * blockDim.x + threadIdx.x; i < B_ * H_; i += gridDim.x * blockDim.x) {
        g_c0[i] = 0.f; g_c1[i] = 0.f;
    }
    for (int i = blockIdx.x * blockDim.x + threadIdx.x; i < H_ * (KXS - F_); i += gridDim.x * blockDim.x) {
        int r = i / (KXS - F_), c = i % (KXS - F_);
        g_WbInp[(size_t)r * KXS + F_ + c] = __float2half(0.f);
    }
}

__global__ void split_X_kernel(const float* __restrict__ X) {
    long n = (long)NBT * KXS;
    for (long i = blockIdx.x * (long)blockDim.x + threadIdx.x; i < n; i += (long)gridDim.x * blockDim.x) {
        long row = i / KXS; int col = (int)(i % KXS);
        g_Xh[i] = (col < F_) ? __float2half_rn(X[row * F_ + col]) : __float2half(0.f);
    }
}

__global__ void split_Winp_kernel(const float* __restrict__ W) {
    int n = H_ * F_;
    for (int i = blockIdx.x * blockDim.x + threadIdx.x; i < n; i += gridDim.x * blockDim.x) {
        int r = i / F_, k = i % F_;
        g_WbInp[(size_t)r * KXS + k] = __float2half_rn(W[i]);
    }
}

// Gate-interleaved fp16 weights: dst row n = j*4+g <- src row r = g*256+j.
// Row layout (768): [W_in | W_hh | W_hh]; fused bias.
__global__ void fuse_W_kernel(const float* __restrict__ Wih, const float* __restrict__ Whh,
                              const float* __restrict__ bih, const float* __restrict__ bhh,
                              __half* __restrict__ Wc, float* __restrict__ biasF)
{
    int total = G4H * H_;
    for (int i = blockIdx.x * blockDim.x + threadIdx.x; i < total; i += gridDim.x * blockDim.x) {
        int n = i >> 8, k = i & 255;
        int j = n >> 2, g = n & 3;
        int r = g * 256 + j;
        __half* row = Wc + (size_t)n * KW;
        __half wi = __float2half_rn(Wih[r * 256 + k]);
        __half wh = __float2half_rn(Whh[r * 256 + k]);
        row[k] = wi;
        row[256 + k] = wh;
        row[512 + k] = wh;
        if (k == 0) biasF[n] = bih[r] + bhh[r];
    }
}

__global__ void __launch_bounds__(256)
proj_kernel(const float* __restrict__ W_out, const float* __restrict__ b_out, float* __restrict__ out)
{
    __shared__ float Ws[O_ * H_];
    __shared__ float bs[O_];
    for (int i = threadIdx.x; i < O_ * H_; i += blockDim.x) Ws[i] = W_out[i];
    if (threadIdx.x < O_) bs[threadIdx.x] = b_out[threadIdx.x];
    __syncthreads();
    int warp = threadIdx.x / 32, lane = threadIdx.x % 32;
    long row = (long)blockIdx.x * 8 + warp;
    if (row >= NBT) return;
    float x[H_ / 32];
#pragma unroll
    for (int j = 0; j < H_ / 32; j++) x[j] = g_hs[row * H_ + lane + 32 * j];
#pragma unroll
    for (int o = 0; o < O_; o++) {
        float s = 0.f;
#pragma unroll
        for (int j = 0; j < H_ / 32; j++) s = fmaf(x[j], Ws[o * H_ + lane + 32 * j], s);
#pragma unroll
        for (int off = 16; off > 0; off >>= 1) s += __shfl_xor_sync(0xffffffffu, s, off);
        if (lane == 0) out[row * O_ + o] = s + bs[o];
    }
}

// ======================= launch =======================
extern "C" void kernel_launch(void* const* d_in, const int* in_sizes, int n_in,
                              void* d_out, int out_size)
{
    (void)in_sizes; (void)n_in; (void)out_size;
    const float* X     = (const float*)d_in[0];
    const float* W_inp = (const float*)d_in[1];
    const float* b_inp = (const float*)d_in[2];
    const float* Wih0  = (const float*)d_in[3];
    const float* Whh0  = (const float*)d_in[4];
    const float* bih0  = (const float*)d_in[5];
    const float* bhh0  = (const float*)d_in[6];
    const float* Wih1  = (const float*)d_in[7];
    const float* Whh1  = (const float*)d_in[8];
    const float* bih1  = (const float*)d_in[9];
    const float* bhh1  = (const float*)d_in[10];
    const float* W_out = (const float*)d_in[11];
    const float* b_out = (const float*)d_in[12];

    float* out     = (float*)d_out;
    float* hn_base = out + (size_t)B_ * T_ * O_;
    float* cn_base = hn_base + (size_t)2 * B_ * H_;

    static bool init = false;
    static __half *Xh, *Axp, *ActA, *ActB, *WbInp, *Wc0, *Wc1;
    static float *c0, *c1, *hs, *bias0, *bias1;
    if (!init) {
        cudaGetSymbolAddress((void**)&Xh,     g_Xh);
        cudaGetSymbolAddress((void**)&Axp,    g_Axp);
        cudaGetSymbolAddress((void**)&ActA,   g_ActA);
        cudaGetSymbolAddress((void**)&ActB,   g_ActB);
        cudaGetSymbolAddress((void**)&WbInp,  g_WbInp);
        cudaGetSymbolAddress((void**)&Wc0,    g_Wc0);
        cudaGetSymbolAddress((void**)&Wc1,    g_Wc1);
        cudaGetSymbolAddress((void**)&c0,     g_c0);
        cudaGetSymbolAddress((void**)&c1,     g_c1);
        cudaGetSymbolAddress((void**)&hs,     g_hs);
        cudaGetSymbolAddress((void**)&bias0,  g_bias0);
        cudaGetSymbolAddress((void**)&bias1,  g_bias1);
        cudaFuncSetAttribute(xp_gemm,   cudaFuncAttributeMaxDynamicSharedMemorySize, SM_TOTAL);
        cudaFuncSetAttribute(gemm_lstm, cudaFuncAttributeMaxDynamicSharedMemorySize, SM_TOTAL);
        init = true;
    }

    // prep
    zero_misc_kernel<<<1024, 256>>>();
    split_X_kernel<<<2048, 256>>>(X);
    split_Winp_kernel<<<256, 256>>>(W_inp);
    fuse_W_kernel<<<512, 256>>>(Wih0, Whh0, bih0, bhh0, Wc0, bias0);
    fuse_W_kernel<<<512, 256>>>(Wih1, Whh1, bih1, bhh1, Wc1, bias1);

    // xp = fp16(X @ W_inp^T + b_inp)
    {
        dim3 grid(H_ / TN_, NBT / TM_);   // (2, 640)
        xp_gemm<<<grid, 256, SM_TOTAL>>>(Xh, WbInp, b_inp, Axp);
    }

    // Recurrence, pipelined across the step boundary:
    //   P:    layer0(0)                          reads ActA (zeros), writes ActB
    //   L_i:  [layer1(i-1), layer0(i)] i=1..9    reads bufR, writes bufW
    //   F:    layer1(9)                          reads ActA
    {
        dim3 g1(8, 64);
        const long ldxp = (long)T_ * AXPW;   // 2560

        // P: layer0(0): [xp(0) | h0(-1)=0]
        gemm_lstm<<<g1, 256, SM_TOTAL>>>(
            Axp, ldxp, ActA,
            Wc0, bias0, c0, ActB, 0,
            nullptr, 0, nullptr, nullptr,
            Axp, ldxp, ActA, Wc0, bias0, c0, ActB, 0,
            nullptr, 0, nullptr, nullptr);

        for (int i = 1; i <= 9; i++) {
            __half* bufR = ((i - 1) % 2 == 0) ? ActB : ActA;
            __half* bufW = ((i - 1) % 2 == 0) ? ActA : ActB;
            int t1 = i - 1;
            int t0 = i;
            bool l0last = (t0 == T_ - 1);
            dim3 g2(16, 64);
            gemm_lstm<<<g2, 256, SM_TOTAL>>>(
                // job0: layer1(t1) = [h0(t1)hi | h1(t1-1) hi,lo]
                bufR, (long)K4H, bufR + 512,
                Wc1, bias1, c1, bufW, 512,
                hs, t1, nullptr, nullptr,
                // job1: layer0(t0) = [xp(t0) | h0(t0-1) hi,lo]
                Axp + (size_t)t0 * AXPW, ldxp, bufR,
                Wc0, bias0, c0, bufW, 0,
                nullptr, t0,
                l0last ? hn_base : nullptr, l0last ? cn_base : nullptr);
        }

        // F: layer1(9); bufW_9 = ActA
        gemm_lstm<<<g1, 256, SM_TOTAL>>>(
            ActA, (long)K4H, ActA + 512,
            Wc1, bias1, c1, ActB, 512,
            hs, T_ - 1, hn_base + (size_t)B_ * H_, cn_base + (size_t)B_ * H_,
            ActA, (long)K4H, ActA + 512, Wc1, bias1, c1, ActB, 512,
            hs, T_ - 1, nullptr, nullptr);
    }

    // outputs = hs @ W_out^T + b_out
    proj_kernel<<<NBT / 8, 256>>>(W_out, b_out, out);
}